// round 7
// baseline (speedup 1.0000x reference)
#include <cuda_runtime.h>
#include <math_constants.h>

// ============================================================================
// ImageMultiheadCrossAttention  (B=8, C=512, HW=4096, d=64, 8 identical heads)
//
// Phase 1 (proj_kernel):  Q/K/V = W (64x512) @ X (512x4096) + bias, per batch.
// Phase 2 (attn_kernel):  flash-style attention per (batch, 64-query tile):
//    S = Q^T K (fp32, f32x2 FMA), online softmax, O += P V^T, broadcast x8 heads.
// All math fp32 (matches reference within ~1e-6).
// ============================================================================

#define BATCH 8
#define CCH   512
#define DH    64
#define HW    4096

// scratch: projected Q,K,V  [b][d][n]
__device__ float g_Q[BATCH * DH * HW];
__device__ float g_K[BATCH * DH * HW];
__device__ float g_V[BATCH * DH * HW];

#define DEVINL __device__ __forceinline__

DEVINL unsigned long long pack2(float x, float y) {
    unsigned long long r;
    asm("mov.b64 %0, {%1, %2};" : "=l"(r) : "f"(x), "f"(y));
    return r;
}
DEVINL void unpack2(unsigned long long p, float& x, float& y) {
    asm("mov.b64 {%0, %1}, %2;" : "=f"(x), "=f"(y) : "l"(p));
}
// d = a * b + d   (packed 2x fp32 FMA — FFMA2, PTX-only on sm_103a)
DEVINL void fma2(unsigned long long& d, unsigned long long a, unsigned long long b) {
    asm("fma.rn.f32x2 %0, %1, %2, %0;" : "+l"(d) : "l"(a), "l"(b));
}
DEVINL void mul2(unsigned long long& d, unsigned long long a) {
    asm("mul.rn.f32x2 %0, %0, %1;" : "+l"(d) : "l"(a));
}

// ----------------------------------------------------------------------------
// Projection: out[b][d][n] = sum_c W[d][c] * X[b][c][n] + bias[d]
// grid (32 n-tiles of 128, 8 batches, 3 projections), 256 threads.
// Block tile: 64 d x 128 n, K-chunks of 32 channels.
// ----------------------------------------------------------------------------
__global__ __launch_bounds__(256) void proj_kernel(
    const float* __restrict__ q, const float* __restrict__ k, const float* __restrict__ v,
    const float* __restrict__ wq, const float* __restrict__ bq,
    const float* __restrict__ wk, const float* __restrict__ bk,
    const float* __restrict__ wv, const float* __restrict__ bv)
{
    const int p = blockIdx.z;
    const float* x  = (p == 0) ? q  : (p == 1) ? k  : v;
    const float* w  = (p == 0) ? wq : (p == 1) ? wk : wv;
    const float* bb = (p == 0) ? bq : (p == 1) ? bk : bv;
    float* out      = (p == 0) ? g_Q : (p == 1) ? g_K : g_V;

    const int b  = blockIdx.y;
    const int n0 = blockIdx.x * 128;

    __shared__ float Xs[32][132];   // [c][n], padded
    __shared__ float Ws[32][68];    // [c][d], padded (transposed weight chunk)

    const int tid = threadIdx.x;
    const int ty = tid >> 4;        // 0..15 -> d = ty*4 + i
    const int tx = tid & 15;        // 0..15 -> n = tx*8 + u

    unsigned long long acc[4][4];   // [i][n-pair]
#pragma unroll
    for (int i = 0; i < 4; i++)
#pragma unroll
        for (int u = 0; u < 4; u++) acc[i][u] = 0ull;   // (0.f, 0.f)

    for (int c0 = 0; c0 < CCH; c0 += 32) {
        __syncthreads();
        // load X chunk [32 c][128 n], coalesced
#pragma unroll
        for (int i = 0; i < 4; i++) {
            int e = tid * 4 + i * 1024;        // 0..4095
            int cc = e >> 7, nn = e & 127;
            *(float4*)&Xs[cc][nn] =
                *(const float4*)&x[(((long)b * CCH + c0 + cc) << 12) + n0 + nn];
        }
        // load W chunk transposed: Ws[c][d] = W[d][c0+c]
#pragma unroll
        for (int i = 0; i < 8; i++) {
            int e = tid + i * 256;             // 0..2047
            int cc = e & 31, dd = e >> 5;
            Ws[cc][dd] = w[(dd << 9) + c0 + cc];
        }
        __syncthreads();

#pragma unroll 4
        for (int cc = 0; cc < 32; cc++) {
            float4 a4 = *(const float4*)&Ws[cc][ty * 4];
            const unsigned long long* bp =
                (const unsigned long long*)&Xs[cc][tx * 8];   // 4 packed n-pairs
            unsigned long long b0 = bp[0], b1 = bp[1], b2 = bp[2], b3 = bp[3];
            unsigned long long as0 = pack2(a4.x, a4.x);
            unsigned long long as1 = pack2(a4.y, a4.y);
            unsigned long long as2 = pack2(a4.z, a4.z);
            unsigned long long as3 = pack2(a4.w, a4.w);
            fma2(acc[0][0], as0, b0); fma2(acc[0][1], as0, b1);
            fma2(acc[0][2], as0, b2); fma2(acc[0][3], as0, b3);
            fma2(acc[1][0], as1, b0); fma2(acc[1][1], as1, b1);
            fma2(acc[1][2], as1, b2); fma2(acc[1][3], as1, b3);
            fma2(acc[2][0], as2, b0); fma2(acc[2][1], as2, b1);
            fma2(acc[2][2], as2, b2); fma2(acc[2][3], as2, b3);
            fma2(acc[3][0], as3, b0); fma2(acc[3][1], as3, b1);
            fma2(acc[3][2], as3, b2); fma2(acc[3][3], as3, b3);
        }
    }

    // epilogue: bias + store [b][d][n0 + tx*8 .. +7]
#pragma unroll
    for (int i = 0; i < 4; i++) {
        int d = ty * 4 + i;
        float bias = bb[d];
        float o[8];
#pragma unroll
        for (int u = 0; u < 4; u++) {
            unpack2(acc[i][u], o[2 * u], o[2 * u + 1]);
            o[2 * u] += bias; o[2 * u + 1] += bias;
        }
        float* dst = &out[(((long)b * DH + d) << 12) + n0 + tx * 8];
        *(float4*)&dst[0] = make_float4(o[0], o[1], o[2], o[3]);
        *(float4*)&dst[4] = make_float4(o[4], o[5], o[6], o[7]);
    }
}

// ----------------------------------------------------------------------------
// Attention: flash over m, 64-query tile per block.
// grid (64 n-tiles, 8 batches), 256 threads (16 ty x 16 tx).
// S tile: 64 n x 32 m   (thread: 4 n x 2 m, packed over m)
// O tile: 64 n x 64 d   (thread: 4 n x 4 d, packed over d)
// ----------------------------------------------------------------------------
__global__ __launch_bounds__(256, 3) void attn_kernel(float* __restrict__ out)
{
    const int b  = blockIdx.y;
    const int n0 = blockIdx.x * 64;

    __shared__ float Qs[64][68];   // [d][n]
    __shared__ float Ks[64][36];   // [d][m]  (36: float2-aligned, conflict-free)
    __shared__ float Vs[64][33];   // [d][m]  (33: scalar reads, 2-way max)
    __shared__ float Ps[32][68];   // [m][n]

    const int tid = threadIdx.x;
    const int ty = tid >> 4;   // n = ty*4 + i
    const int tx = tid & 15;   // S: m = tx*2 + j ; O: d = tx*4 + j

    // load Q tile [64 d][64 n]
#pragma unroll
    for (int i = 0; i < 4; i++) {
        int e = tid * 4 + i * 1024;
        int d = e >> 6, n = e & 63;
        *(float4*)&Qs[d][n] = *(const float4*)&g_Q[(((long)b * DH + d) << 12) + n0 + n];
    }

    float mrun[4] = {-CUDART_INF_F, -CUDART_INF_F, -CUDART_INF_F, -CUDART_INF_F};
    float lrun[4] = {0.f, 0.f, 0.f, 0.f};
    unsigned long long accO[4][2];
#pragma unroll
    for (int i = 0; i < 4; i++) { accO[i][0] = 0ull; accO[i][1] = 0ull; }

    for (int m0 = 0; m0 < HW; m0 += 32) {
        __syncthreads();
        // load K,V tiles [64 d][32 m]
#pragma unroll
        for (int i = 0; i < 2; i++) {
            int e = tid * 4 + i * 1024;
            int d = e >> 5, m = e & 31;
            *(float4*)&Ks[d][m] = *(const float4*)&g_K[(((long)b * DH + d) << 12) + m0 + m];
            float4 v4 = *(const float4*)&g_V[(((long)b * DH + d) << 12) + m0 + m];
            Vs[d][m + 0] = v4.x; Vs[d][m + 1] = v4.y;
            Vs[d][m + 2] = v4.z; Vs[d][m + 3] = v4.w;
        }
        __syncthreads();

        // S = Q^T K : accS[i] = packed (S[n_i][m0'], S[n_i][m0'+1])
        unsigned long long accS[4] = {0ull, 0ull, 0ull, 0ull};
#pragma unroll 4
        for (int d = 0; d < 64; d++) {
            float4 a4 = *(const float4*)&Qs[d][ty * 4];
            unsigned long long bp = *(const unsigned long long*)&Ks[d][tx * 2];
            fma2(accS[0], pack2(a4.x, a4.x), bp);
            fma2(accS[1], pack2(a4.y, a4.y), bp);
            fma2(accS[2], pack2(a4.z, a4.z), bp);
            fma2(accS[3], pack2(a4.w, a4.w), bp);
        }

        // online softmax (per row: reduce across the 16 tx lanes, width-16 shuffles)
#pragma unroll
        for (int i = 0; i < 4; i++) {
            float s0, s1;
            unpack2(accS[i], s0, s1);
            float mx = fmaxf(s0, s1);
#pragma unroll
            for (int off = 8; off >= 1; off >>= 1)
                mx = fmaxf(mx, __shfl_xor_sync(0xffffffffu, mx, off, 16));
            float mnew = fmaxf(mrun[i], mx);
            float sc = __expf(mrun[i] - mnew);
            float p0 = __expf(s0 - mnew);
            float p1 = __expf(s1 - mnew);
            float sum = p0 + p1;
#pragma unroll
            for (int off = 8; off >= 1; off >>= 1)
                sum += __shfl_xor_sync(0xffffffffu, sum, off, 16);
            lrun[i] = lrun[i] * sc + sum;
            mrun[i] = mnew;
            unsigned long long scp = pack2(sc, sc);
            mul2(accO[i][0], scp);
            mul2(accO[i][1], scp);
            Ps[tx * 2 + 0][ty * 4 + i] = p0;
            Ps[tx * 2 + 1][ty * 4 + i] = p1;
        }
        __syncthreads();

        // O += P V^T : accO[i][p] = packed over d-pairs (tx*4+2p, tx*4+2p+1)
#pragma unroll 2
        for (int m = 0; m < 32; m++) {
            float4 a4 = *(const float4*)&Ps[m][ty * 4];
            float v0 = Vs[tx * 4 + 0][m];
            float v1 = Vs[tx * 4 + 1][m];
            float v2 = Vs[tx * 4 + 2][m];
            float v3 = Vs[tx * 4 + 3][m];
            unsigned long long vp0 = pack2(v0, v1);
            unsigned long long vp1 = pack2(v2, v3);
            unsigned long long a0 = pack2(a4.x, a4.x);
            unsigned long long a1 = pack2(a4.y, a4.y);
            unsigned long long a2 = pack2(a4.z, a4.z);
            unsigned long long a3 = pack2(a4.w, a4.w);
            fma2(accO[0][0], a0, vp0); fma2(accO[0][1], a0, vp1);
            fma2(accO[1][0], a1, vp0); fma2(accO[1][1], a1, vp1);
            fma2(accO[2][0], a2, vp0); fma2(accO[2][1], a2, vp1);
            fma2(accO[3][0], a3, vp0); fma2(accO[3][1], a3, vp1);
        }
    }

    // normalize, stage through smem (reuse Qs as Os[d][n]), broadcast to 8 heads
    __syncthreads();
#pragma unroll
    for (int i = 0; i < 4; i++) {
        float inv = 1.0f / lrun[i];
        float o0, o1, o2, o3;
        unpack2(accO[i][0], o0, o1);
        unpack2(accO[i][1], o2, o3);
        int n = ty * 4 + i;
        Qs[tx * 4 + 0][n] = o0 * inv;
        Qs[tx * 4 + 1][n] = o1 * inv;
        Qs[tx * 4 + 2][n] = o2 * inv;
        Qs[tx * 4 + 3][n] = o3 * inv;
    }
    __syncthreads();
#pragma unroll
    for (int i = 0; i < 4; i++) {
        int e = tid * 4 + i * 1024;
        int d = e >> 6, n = e & 63;
        float4 val = *(const float4*)&Qs[d][n];
#pragma unroll
        for (int h = 0; h < 8; h++) {
            *(float4*)&out[(((long)b * CCH + h * DH + d) << 12) + n0 + n] = val;
        }
    }
}

// ----------------------------------------------------------------------------
extern "C" void kernel_launch(void* const* d_in, const int* in_sizes, int n_in,
                              void* d_out, int out_size)
{
    const float* q  = (const float*)d_in[0];
    const float* k  = (const float*)d_in[1];
    const float* v  = (const float*)d_in[2];
    const float* wq = (const float*)d_in[3];
    const float* bq = (const float*)d_in[4];
    const float* wk = (const float*)d_in[5];
    const float* bk = (const float*)d_in[6];
    const float* wv = (const float*)d_in[7];
    const float* bv = (const float*)d_in[8];
    float* out = (float*)d_out;

    dim3 gp(HW / 128, BATCH, 3);
    proj_kernel<<<gp, 256>>>(q, k, v, wq, bq, wk, bk, wv, bv);

    dim3 ga(HW / 64, BATCH);
    attn_kernel<<<ga, 256>>>(out);
}

// round 8
// speedup vs baseline: 2.9048x; 2.9048x over previous
#include <cuda_runtime.h>
#include <cuda_fp16.h>
#include <math_constants.h>

// ============================================================================
// ImageMultiheadCrossAttention  (B=8, C=512, HW=4096, d=64, 8 identical heads)
//
// proj:  Q/K/V = W(64x512) @ X(512x4096) + bias (fp32 FFMA2), emitted as
//        split fp16 (hi + lo) planes:  Q,K -> [b][seq][64],  V -> [b][64][seq].
// attn:  flash attention, tensor cores (mma.sync m16n8k16 f16->f32),
//        3-pass hi/lo split for both S=QK^T and O=PV  => exact to ~1e-6.
//        Block: 128 queries (8 warps), 32-key tiles. Broadcast x8 heads.
// ============================================================================

#define BATCH 8
#define CCH   512
#define DH    64
#define HW    4096

// split-fp16 projected tensors
__device__ __half g_Qh[BATCH * HW * DH];   // [b][n][d]
__device__ __half g_Ql[BATCH * HW * DH];
__device__ __half g_Kh[BATCH * HW * DH];   // [b][m][d]
__device__ __half g_Kl[BATCH * HW * DH];
__device__ __half g_Vh[BATCH * DH * HW];   // [b][d][m]
__device__ __half g_Vl[BATCH * DH * HW];

#define DEVINL __device__ __forceinline__

DEVINL unsigned long long pack2(float x, float y) {
    unsigned long long r;
    asm("mov.b64 %0, {%1, %2};" : "=l"(r) : "f"(x), "f"(y));
    return r;
}
DEVINL void unpack2(unsigned long long p, float& x, float& y) {
    asm("mov.b64 {%0, %1}, %2;" : "=f"(x), "=f"(y) : "l"(p));
}
DEVINL void fma2(unsigned long long& d, unsigned long long a, unsigned long long b) {
    asm("fma.rn.f32x2 %0, %1, %2, %0;" : "+l"(d) : "l"(a), "l"(b));
}

DEVINL void mma16816(float& d0, float& d1, float& d2, float& d3,
                     unsigned a0, unsigned a1, unsigned a2, unsigned a3,
                     unsigned b0, unsigned b1) {
    asm("mma.sync.aligned.m16n8k16.row.col.f32.f16.f16.f32 "
        "{%0,%1,%2,%3}, {%4,%5,%6,%7}, {%8,%9}, {%0,%1,%2,%3};"
        : "+f"(d0), "+f"(d1), "+f"(d2), "+f"(d3)
        : "r"(a0), "r"(a1), "r"(a2), "r"(a3), "r"(b0), "r"(b1));
}

DEVINL unsigned h2u(__half2 h) { return *reinterpret_cast<unsigned*>(&h); }

// ----------------------------------------------------------------------------
// Projection. grid (32 n-tiles x 8 batches x 3), 256 threads.
// Tile 64d x 128n, K-chunks of 32. Xs bank-conflict-free mapping: n = tx*2+u*32.
// ----------------------------------------------------------------------------
__global__ __launch_bounds__(256) void proj_kernel(
    const float* __restrict__ q, const float* __restrict__ k, const float* __restrict__ v,
    const float* __restrict__ wq, const float* __restrict__ bq,
    const float* __restrict__ wk, const float* __restrict__ bk,
    const float* __restrict__ wv, const float* __restrict__ bv)
{
    const int p = blockIdx.z;
    const float* x  = (p == 0) ? q  : (p == 1) ? k  : v;
    const float* w  = (p == 0) ? wq : (p == 1) ? wk : wv;
    const float* bb = (p == 0) ? bq : (p == 1) ? bk : bv;

    const int b  = blockIdx.y;
    const int n0 = blockIdx.x * 128;

    __shared__ float Xs[32][132];
    __shared__ float Ws[32][68];

    const int tid = threadIdx.x;
    const int ty = tid >> 4;        // d = ty*4 + i
    const int tx = tid & 15;        // n = tx*2 + {0,1} + u*32

    unsigned long long acc[4][4];
#pragma unroll
    for (int i = 0; i < 4; i++)
#pragma unroll
        for (int u = 0; u < 4; u++) acc[i][u] = 0ull;

    for (int c0 = 0; c0 < CCH; c0 += 32) {
        __syncthreads();
#pragma unroll
        for (int i = 0; i < 4; i++) {
            int e = tid * 4 + i * 1024;
            int cc = e >> 7, nn = e & 127;
            *(float4*)&Xs[cc][nn] =
                *(const float4*)&x[(((long)b * CCH + c0 + cc) << 12) + n0 + nn];
        }
#pragma unroll
        for (int i = 0; i < 8; i++) {
            int e = tid + i * 256;
            int cc = e & 31, dd = e >> 5;
            Ws[cc][dd] = w[(dd << 9) + c0 + cc];
        }
        __syncthreads();

#pragma unroll 4
        for (int cc = 0; cc < 32; cc++) {
            float4 a4 = *(const float4*)&Ws[cc][ty * 4];
            unsigned long long b0 = *(const unsigned long long*)&Xs[cc][tx * 2 + 0];
            unsigned long long b1 = *(const unsigned long long*)&Xs[cc][tx * 2 + 32];
            unsigned long long b2 = *(const unsigned long long*)&Xs[cc][tx * 2 + 64];
            unsigned long long b3 = *(const unsigned long long*)&Xs[cc][tx * 2 + 96];
            unsigned long long as0 = pack2(a4.x, a4.x);
            unsigned long long as1 = pack2(a4.y, a4.y);
            unsigned long long as2 = pack2(a4.z, a4.z);
            unsigned long long as3 = pack2(a4.w, a4.w);
            fma2(acc[0][0], as0, b0); fma2(acc[0][1], as0, b1);
            fma2(acc[0][2], as0, b2); fma2(acc[0][3], as0, b3);
            fma2(acc[1][0], as1, b0); fma2(acc[1][1], as1, b1);
            fma2(acc[1][2], as1, b2); fma2(acc[1][3], as1, b3);
            fma2(acc[2][0], as2, b0); fma2(acc[2][1], as2, b1);
            fma2(acc[2][2], as2, b2); fma2(acc[2][3], as2, b3);
            fma2(acc[3][0], as3, b0); fma2(acc[3][1], as3, b1);
            fma2(acc[3][2], as3, b2); fma2(acc[3][3], as3, b3);
        }
    }

    // epilogue: bias, split fp16, store
#pragma unroll
    for (int i = 0; i < 4; i++) {
        int d = ty * 4 + i;
        float bias = bb[d];
#pragma unroll
        for (int u = 0; u < 4; u++) {
            float v0, v1;
            unpack2(acc[i][u], v0, v1);
            v0 += bias; v1 += bias;
            int n = n0 + tx * 2 + u * 32;
            __half h0 = __float2half_rn(v0);
            __half l0 = __float2half_rn(v0 - __half2float(h0));
            __half h1 = __float2half_rn(v1);
            __half l1 = __float2half_rn(v1 - __half2float(h1));
            if (p == 0) {
                g_Qh[(((long)b << 12) + n) * 64 + d] = h0;
                g_Qh[(((long)b << 12) + n + 1) * 64 + d] = h1;
                g_Ql[(((long)b << 12) + n) * 64 + d] = l0;
                g_Ql[(((long)b << 12) + n + 1) * 64 + d] = l1;
            } else if (p == 1) {
                g_Kh[(((long)b << 12) + n) * 64 + d] = h0;
                g_Kh[(((long)b << 12) + n + 1) * 64 + d] = h1;
                g_Kl[(((long)b << 12) + n) * 64 + d] = l0;
                g_Kl[(((long)b << 12) + n + 1) * 64 + d] = l1;
            } else {
                long off = (((long)b << 6) + d) * 4096 + n;
                *(__half2*)&g_Vh[off] = __halves2half2(h0, h1);
                *(__half2*)&g_Vl[off] = __halves2half2(l0, l1);
            }
        }
    }
}

// ----------------------------------------------------------------------------
// Attention, tensor cores. grid (32 q-tiles x 8 batches), 256 threads (8 warps).
// Warp w owns query rows [16w, 16w+16). Key tiles of 32.
// ----------------------------------------------------------------------------
__global__ __launch_bounds__(256, 2) void attn_kernel(float* __restrict__ out)
{
    const int b  = blockIdx.y;
    const int n0 = blockIdx.x * 128;

    // smem: K tiles [32][72] hi/lo, V tiles [64][40] hi/lo; reused as fp32 stage
    __shared__ __align__(16) unsigned char smem_raw[19968];
    __half* Ksh = (__half*)smem_raw;                    // 32*72 = 2304 halves
    __half* Ksl = Ksh + 32 * 72;
    __half* Vsh = (__half*)(smem_raw + 9216);           // 64*40 = 2560 halves
    __half* Vsl = Vsh + 64 * 40;
    float*  stage = (float*)smem_raw;                   // 64 x 68 floats (17408B)

    const int tid  = threadIdx.x;
    const int lane = tid & 31;
    const int w    = tid >> 5;
    const int g    = lane >> 2;   // 0..7
    const int qq   = lane & 3;    // 0..3

    // --- Q fragments (persistent, registers). A-frag layout m16k16. ---
    unsigned QAh[4][4], QAl[4][4];
    {
        const int r0 = n0 + 16 * w + g;
#pragma unroll
        for (int ks = 0; ks < 4; ks++) {
            int c = 16 * ks + 2 * qq;
            long base0 = (((long)b << 12) + r0) * 64;
            long base1 = (((long)b << 12) + r0 + 8) * 64;
            QAh[ks][0] = *(const unsigned*)&g_Qh[base0 + c];
            QAh[ks][1] = *(const unsigned*)&g_Qh[base1 + c];
            QAh[ks][2] = *(const unsigned*)&g_Qh[base0 + c + 8];
            QAh[ks][3] = *(const unsigned*)&g_Qh[base1 + c + 8];
            QAl[ks][0] = *(const unsigned*)&g_Ql[base0 + c];
            QAl[ks][1] = *(const unsigned*)&g_Ql[base1 + c];
            QAl[ks][2] = *(const unsigned*)&g_Ql[base0 + c + 8];
            QAl[ks][3] = *(const unsigned*)&g_Ql[base1 + c + 8];
        }
    }

    float accO[8][4];
#pragma unroll
    for (int t = 0; t < 8; t++)
#pragma unroll
        for (int e = 0; e < 4; e++) accO[t][e] = 0.f;
    float mrun0 = -CUDART_INF_F, mrun1 = -CUDART_INF_F;
    float lrun0 = 0.f, lrun1 = 0.f;

    const int idx = tid * 8;
    const int kmi = idx >> 6, kdd = idx & 63;    // K tile: [mi][d]
    const int vdv = idx >> 5, vmj = idx & 31;    // V tile: [d][mj]

    for (int m0 = 0; m0 < HW; m0 += 32) {
        __syncthreads();
        // load K (hi/lo) [32 m][64 d] and V (hi/lo) [64 d][32 m]
        {
            long kg = (((long)b << 12) + m0 + kmi) * 64 + kdd;
            *(uint4*)&Ksh[kmi * 72 + kdd] = *(const uint4*)&g_Kh[kg];
            *(uint4*)&Ksl[kmi * 72 + kdd] = *(const uint4*)&g_Kl[kg];
            long vg = (((long)b << 6) + vdv) * 4096 + m0 + vmj;
            *(uint4*)&Vsh[vdv * 40 + vmj] = *(const uint4*)&g_Vh[vg];
            *(uint4*)&Vsl[vdv * 40 + vmj] = *(const uint4*)&g_Vl[vg];
        }
        __syncthreads();

        // --- S = Q K^T, 3-pass split, fp32 acc. 4 m-tiles of 8. ---
        float S[4][4];
#pragma unroll
        for (int t = 0; t < 4; t++)
#pragma unroll
            for (int e = 0; e < 4; e++) S[t][e] = 0.f;

#pragma unroll
        for (int ks = 0; ks < 4; ks++) {
#pragma unroll
            for (int t = 0; t < 4; t++) {
                int row = (8 * t + g) * 72 + 16 * ks + 2 * qq;
                unsigned bh0 = *(const unsigned*)&Ksh[row];
                unsigned bh1 = *(const unsigned*)&Ksh[row + 8];
                mma16816(S[t][0], S[t][1], S[t][2], S[t][3],
                         QAh[ks][0], QAh[ks][1], QAh[ks][2], QAh[ks][3], bh0, bh1);
                mma16816(S[t][0], S[t][1], S[t][2], S[t][3],
                         QAl[ks][0], QAl[ks][1], QAl[ks][2], QAl[ks][3], bh0, bh1);
                unsigned bl0 = *(const unsigned*)&Ksl[row];
                unsigned bl1 = *(const unsigned*)&Ksl[row + 8];
                mma16816(S[t][0], S[t][1], S[t][2], S[t][3],
                         QAh[ks][0], QAh[ks][1], QAh[ks][2], QAh[ks][3], bl0, bl1);
            }
        }

        // --- online softmax (rows g and g+8; quad reduction) ---
        float mx0 = S[0][0], mx1 = S[0][2];
#pragma unroll
        for (int t = 0; t < 4; t++) {
            mx0 = fmaxf(mx0, fmaxf(S[t][0], S[t][1]));
            mx1 = fmaxf(mx1, fmaxf(S[t][2], S[t][3]));
        }
        mx0 = fmaxf(mx0, __shfl_xor_sync(0xffffffffu, mx0, 1));
        mx0 = fmaxf(mx0, __shfl_xor_sync(0xffffffffu, mx0, 2));
        mx1 = fmaxf(mx1, __shfl_xor_sync(0xffffffffu, mx1, 1));
        mx1 = fmaxf(mx1, __shfl_xor_sync(0xffffffffu, mx1, 2));
        float mn0 = fmaxf(mrun0, mx0), mn1 = fmaxf(mrun1, mx1);
        float sc0 = __expf(mrun0 - mn0), sc1 = __expf(mrun1 - mn1);

        float P[4][4];
        float sum0 = 0.f, sum1 = 0.f;
#pragma unroll
        for (int t = 0; t < 4; t++) {
            P[t][0] = __expf(S[t][0] - mn0);
            P[t][1] = __expf(S[t][1] - mn0);
            P[t][2] = __expf(S[t][2] - mn1);
            P[t][3] = __expf(S[t][3] - mn1);
            sum0 += P[t][0] + P[t][1];
            sum1 += P[t][2] + P[t][3];
        }
        sum0 += __shfl_xor_sync(0xffffffffu, sum0, 1);
        sum0 += __shfl_xor_sync(0xffffffffu, sum0, 2);
        sum1 += __shfl_xor_sync(0xffffffffu, sum1, 1);
        sum1 += __shfl_xor_sync(0xffffffffu, sum1, 2);
        lrun0 = lrun0 * sc0 + sum0;
        lrun1 = lrun1 * sc1 + sum1;
        mrun0 = mn0; mrun1 = mn1;
#pragma unroll
        for (int t = 0; t < 8; t++) {
            accO[t][0] *= sc0; accO[t][1] *= sc0;
            accO[t][2] *= sc1; accO[t][3] *= sc1;
        }

        // --- P -> split fp16 A-fragments (C layout == A layout) ---
        unsigned PAh[2][4], PAl[2][4];
#pragma unroll
        for (int j = 0; j < 2; j++) {
#pragma unroll
            for (int half = 0; half < 2; half++) {   // tiles 2j, 2j+1
                int t = 2 * j + half;
                __half h00 = __float2half_rn(P[t][0]);
                __half h01 = __float2half_rn(P[t][1]);
                __half h10 = __float2half_rn(P[t][2]);
                __half h11 = __float2half_rn(P[t][3]);
                __half l00 = __float2half_rn(P[t][0] - __half2float(h00));
                __half l01 = __float2half_rn(P[t][1] - __half2float(h01));
                __half l10 = __float2half_rn(P[t][2] - __half2float(h10));
                __half l11 = __float2half_rn(P[t][3] - __half2float(h11));
                PAh[j][2 * half + 0] = h2u(__halves2half2(h00, h01));
                PAh[j][2 * half + 1] = h2u(__halves2half2(h10, h11));
                PAl[j][2 * half + 0] = h2u(__halves2half2(l00, l01));
                PAl[j][2 * half + 1] = h2u(__halves2half2(l10, l11));
            }
        }
        // A-frag order must be {a0,a1,a2,a3} = {(r,k),(r+8,k),(r,k+8),(r+8,k+8)}
        // built above: index 0=(r, tile2j), 1=(r+8, tile2j), 2=(r, tile2j+1), 3=(r+8,...)
        // which matches k and k+8 halves. OK.

        // --- O += P V, 3-pass split. 8 d-tiles of 8. ---
#pragma unroll
        for (int j = 0; j < 2; j++) {
#pragma unroll
            for (int t = 0; t < 8; t++) {
                int row = (8 * t + g) * 40 + 16 * j + 2 * qq;
                unsigned bh0 = *(const unsigned*)&Vsh[row];
                unsigned bh1 = *(const unsigned*)&Vsh[row + 8];
                mma16816(accO[t][0], accO[t][1], accO[t][2], accO[t][3],
                         PAh[j][0], PAh[j][1], PAh[j][2], PAh[j][3], bh0, bh1);
                mma16816(accO[t][0], accO[t][1], accO[t][2], accO[t][3],
                         PAl[j][0], PAl[j][1], PAl[j][2], PAl[j][3], bh0, bh1);
                unsigned bl0 = *(const unsigned*)&Vsl[row];
                unsigned bl1 = *(const unsigned*)&Vsl[row + 8];
                mma16816(accO[t][0], accO[t][1], accO[t][2], accO[t][3],
                         PAh[j][0], PAh[j][1], PAh[j][2], PAh[j][3], bl0, bl1);
            }
        }
    }

    // normalize
    {
        float inv0 = 1.0f / lrun0, inv1 = 1.0f / lrun1;
#pragma unroll
        for (int t = 0; t < 8; t++) {
            accO[t][0] *= inv0; accO[t][1] *= inv0;
            accO[t][2] *= inv1; accO[t][3] *= inv1;
        }
    }

    // epilogue: stage 64n-half at a time in smem [d][n], write coalesced x8 heads
#pragma unroll
    for (int hhalf = 0; hhalf < 2; hhalf++) {
        __syncthreads();
        if ((w >> 2) == hhalf) {
            int rloc = 16 * (w & 3) + g;
#pragma unroll
            for (int t = 0; t < 8; t++) {
                int d = 8 * t + 2 * qq;
                stage[d * 68 + rloc]     = accO[t][0];
                stage[(d + 1) * 68 + rloc] = accO[t][1];
                stage[d * 68 + rloc + 8]   = accO[t][2];
                stage[(d + 1) * 68 + rloc + 8] = accO[t][3];
            }
        }
        __syncthreads();
        int dd = tid >> 2, nc = (tid & 3) * 16;
        float4 v0 = *(float4*)&stage[dd * 68 + nc + 0];
        float4 v1 = *(float4*)&stage[dd * 68 + nc + 4];
        float4 v2 = *(float4*)&stage[dd * 68 + nc + 8];
        float4 v3 = *(float4*)&stage[dd * 68 + nc + 12];
#pragma unroll
        for (int h = 0; h < 8; h++) {
            float* dst = &out[(((long)b * CCH + h * DH + dd) << 12) + n0 + hhalf * 64 + nc];
            *(float4*)&dst[0] = v0;
            *(float4*)&dst[4] = v1;
            *(float4*)&dst[8] = v2;
            *(float4*)&dst[12] = v3;
        }
    }
}

// ----------------------------------------------------------------------------
extern "C" void kernel_launch(void* const* d_in, const int* in_sizes, int n_in,
                              void* d_out, int out_size)
{
    const float* q  = (const float*)d_in[0];
    const float* k  = (const float*)d_in[1];
    const float* v  = (const float*)d_in[2];
    const float* wq = (const float*)d_in[3];
    const float* bq = (const float*)d_in[4];
    const float* wk = (const float*)d_in[5];
    const float* bk = (const float*)d_in[6];
    const float* wv = (const float*)d_in[7];
    const float* bv = (const float*)d_in[8];
    float* out = (float*)d_out;

    dim3 gp(HW / 128, BATCH, 3);
    proj_kernel<<<gp, 256>>>(q, k, v, wq, bq, wk, bk, wv, bv);

    dim3 ga(HW / 128, BATCH);
    attn_kernel<<<ga, 256>>>(out);
}